// round 1
// baseline (speedup 1.0000x reference)
#include <cuda_runtime.h>
#include <math.h>

// Problem constants (fixed by the dataset)
#define T_TOK 4096
#define HID   1024
#define NE    16
#define FE    512
#define FS    2048
#define NPAIR (T_TOK * 2)

// ---------------------------------------------------------------------------
// Scratch: __device__ globals (allocation-free per harness rules)
// ---------------------------------------------------------------------------
__device__ float g_gate_s[(size_t)T_TOK * FS];   // shared gate, then inter (in-place)
__device__ float g_up_s[(size_t)T_TOK * FS];     // shared up
__device__ float g_gate_r[(size_t)NPAIR * FE];   // routed gate, then inter (in-place)
__device__ float g_up_r[(size_t)NPAIR * FE];     // routed up
__device__ float g_routed[(size_t)NPAIR * HID];  // per-pair routed output (pre-sum)
__device__ int   g_cnt[NE];                      // tokens-pairs per expert
__device__ int   g_bucket[NE * T_TOK];           // pair ids grouped by expert
__device__ float g_pw[NPAIR];                    // per-pair router weight

// ---------------------------------------------------------------------------
// Router: one warp per token. logits = x[t] @ router_w, softmax, top-2.
// Buckets pairs by expert via int atomics (bucket ORDER is nondeterministic,
// but every pair computes/writes its own rows, so the final output is
// bitwise deterministic).
// ---------------------------------------------------------------------------
__global__ void zero_counts_kernel() {
    if (threadIdx.x < NE) g_cnt[threadIdx.x] = 0;
}

__global__ void router_kernel(const float* __restrict__ x,
                              const float* __restrict__ rw) {
    int warp = threadIdx.x >> 5;
    int lane = threadIdx.x & 31;
    int t = blockIdx.x * (blockDim.x >> 5) + warp;
    if (t >= T_TOK) return;

    float acc[NE];
#pragma unroll
    for (int e = 0; e < NE; e++) acc[e] = 0.0f;

    const float* xr = x + (size_t)t * HID;
    for (int d = lane; d < HID; d += 32) {
        float xv = xr[d];
        const float* r = rw + (size_t)d * NE;
#pragma unroll
        for (int e = 0; e < NE; e++) acc[e] = fmaf(xv, r[e], acc[e]);
    }
#pragma unroll
    for (int e = 0; e < NE; e++) {
#pragma unroll
        for (int off = 16; off; off >>= 1)
            acc[e] += __shfl_xor_sync(0xffffffffu, acc[e], off);
    }

    if (lane == 0) {
        float mx = acc[0];
#pragma unroll
        for (int e = 1; e < NE; e++) mx = fmaxf(mx, acc[e]);
        float p[NE];
        float s = 0.0f;
#pragma unroll
        for (int e = 0; e < NE; e++) { p[e] = expf(acc[e] - mx); s += p[e]; }
        float inv = 1.0f / s;
#pragma unroll
        for (int e = 0; e < NE; e++) p[e] *= inv;

        // top-1 (first index on tie, matching jax.lax.top_k)
        int   i0 = 0; float w0 = p[0];
#pragma unroll
        for (int e = 1; e < NE; e++) if (p[e] > w0) { w0 = p[e]; i0 = e; }
        // top-2
        int   i1 = -1; float w1 = -1.0f;
#pragma unroll
        for (int e = 0; e < NE; e++)
            if (e != i0 && p[e] > w1) { w1 = p[e]; i1 = e; }

        int pos0 = atomicAdd(&g_cnt[i0], 1);
        g_bucket[i0 * T_TOK + pos0] = 2 * t;
        int pos1 = atomicAdd(&g_cnt[i1], 1);
        g_bucket[i1 * T_TOK + pos1] = 2 * t + 1;
        g_pw[2 * t]     = w0;
        g_pw[2 * t + 1] = w1;
    }
}

// ---------------------------------------------------------------------------
// SGEMM 128x128x8, 256 threads, 8x8 register microtile, double-buffered smem.
// C[M,N] = A[M,K] @ B[K,N] (all row-major; K % 8 == 0; N % 128 == 0).
// MODE 0: plain.
// MODE 1: per-expert gather of x rows (A row = x[pair>>1]), scatter C rows to
//         pair index. B/C sized per expert via blockIdx.z.
// MODE 2: per-expert gather of inter rows (A row = pair), scale rows by router
//         weight, scatter to pair index.
// ---------------------------------------------------------------------------
template <int MODE>
__global__ __launch_bounds__(256)
void sgemm128_kernel(const float* __restrict__ A,
                     const float* __restrict__ B,
                     float* __restrict__ C,
                     int M, int N, int K) {
    int e = blockIdx.z;
    int m_rows = M;
    const int* rowlist = nullptr;
    if (MODE != 0) {
        m_rows  = g_cnt[e];
        rowlist = g_bucket + e * T_TOK;
        B += (size_t)e * K * N;
    }
    const int m0 = blockIdx.y * 128;
    const int n0 = blockIdx.x * 128;
    if (m0 >= m_rows) return;

    __shared__ float As[2][8][128];
    __shared__ float Bs[2][8][128];

    const int tid = threadIdx.x;
    // A tile loader mapping: 128 rows x 8 cols, float4 per thread
    const int ar = tid >> 1;          // 0..127
    const int ac = (tid & 1) * 4;     // 0 or 4
    // B tile loader mapping: 8 rows x 128 cols, float4 per thread
    const int br = tid >> 5;          // 0..7
    const int bc = (tid & 31) * 4;    // 0..124

    const int  arow_g = m0 + ar;
    const bool avalid = arow_g < m_rows;
    const int  aidx   = avalid ? arow_g : (m_rows - 1);  // clamp (safe addr)
    const float* Arow;
    if (MODE == 0)      Arow = A + (size_t)aidx * K;
    else if (MODE == 1) Arow = A + (size_t)(rowlist[aidx] >> 1) * K;
    else                Arow = A + (size_t)rowlist[aidx] * K;

    // Prefetch tile 0
    {
        float4 av = avalid ? *(const float4*)(Arow + ac) : make_float4(0, 0, 0, 0);
        As[0][ac + 0][ar] = av.x;
        As[0][ac + 1][ar] = av.y;
        As[0][ac + 2][ar] = av.z;
        As[0][ac + 3][ar] = av.w;
        float4 bv = *(const float4*)(B + (size_t)br * N + n0 + bc);
        *(float4*)&Bs[0][br][bc] = bv;
    }
    __syncthreads();

    float acc[8][8];
#pragma unroll
    for (int i = 0; i < 8; i++)
#pragma unroll
        for (int j = 0; j < 8; j++) acc[i][j] = 0.0f;

    const int ty = tid >> 4, tx = tid & 15;
    const int rm = ty * 8, cn = tx * 8;

    const int KT = K >> 3;
    float4 aP = make_float4(0, 0, 0, 0), bP = make_float4(0, 0, 0, 0);

    for (int kt = 0; kt < KT; kt++) {
        const int cur = kt & 1;
        if (kt + 1 < KT) {
            const int k0 = (kt + 1) * 8;
            aP = avalid ? *(const float4*)(Arow + k0 + ac) : make_float4(0, 0, 0, 0);
            bP = *(const float4*)(B + (size_t)(k0 + br) * N + n0 + bc);
        }
#pragma unroll
        for (int kk = 0; kk < 8; kk++) {
            float4 a0 = *(const float4*)&As[cur][kk][rm];
            float4 a1 = *(const float4*)&As[cur][kk][rm + 4];
            float4 b0 = *(const float4*)&Bs[cur][kk][cn];
            float4 b1 = *(const float4*)&Bs[cur][kk][cn + 4];
            float av[8] = {a0.x, a0.y, a0.z, a0.w, a1.x, a1.y, a1.z, a1.w};
            float bv[8] = {b0.x, b0.y, b0.z, b0.w, b1.x, b1.y, b1.z, b1.w};
#pragma unroll
            for (int i = 0; i < 8; i++)
#pragma unroll
                for (int j = 0; j < 8; j++)
                    acc[i][j] = fmaf(av[i], bv[j], acc[i][j]);
        }
        if (kt + 1 < KT) {
            const int nxt = cur ^ 1;
            As[nxt][ac + 0][ar] = aP.x;
            As[nxt][ac + 1][ar] = aP.y;
            As[nxt][ac + 2][ar] = aP.z;
            As[nxt][ac + 3][ar] = aP.w;
            *(float4*)&Bs[nxt][br][bc] = bP;
        }
        __syncthreads();
    }

    // Epilogue: per-row pointer + optional row scale
#pragma unroll
    for (int i = 0; i < 8; i++) {
        const int row = m0 + rm + i;
        if (row >= m_rows) break;
        float* Crow;
        float scale = 1.0f;
        if (MODE == 0) {
            Crow = C + (size_t)row * N;
        } else {
            const int p = rowlist[row];
            Crow = C + (size_t)p * N;
            if (MODE == 2) scale = g_pw[p];
        }
        float4 o0 = make_float4(acc[i][0] * scale, acc[i][1] * scale,
                                acc[i][2] * scale, acc[i][3] * scale);
        float4 o1 = make_float4(acc[i][4] * scale, acc[i][5] * scale,
                                acc[i][6] * scale, acc[i][7] * scale);
        *(float4*)(Crow + n0 + cn)     = o0;
        *(float4*)(Crow + n0 + cn + 4) = o1;
    }
}

// ---------------------------------------------------------------------------
// Elementwise: g = silu(g) * u  (in-place into g), float4-vectorized.
// ---------------------------------------------------------------------------
__global__ void silu_mul_kernel(float* __restrict__ g,
                                const float* __restrict__ u, int n4) {
    int i = blockIdx.x * blockDim.x + threadIdx.x;
    if (i >= n4) return;
    float4 gv = ((const float4*)g)[i];
    float4 uv = ((const float4*)u)[i];
    gv.x = gv.x / (1.0f + expf(-gv.x)) * uv.x;
    gv.y = gv.y / (1.0f + expf(-gv.y)) * uv.y;
    gv.z = gv.z / (1.0f + expf(-gv.z)) * uv.z;
    gv.w = gv.w / (1.0f + expf(-gv.w)) * uv.w;
    ((float4*)g)[i] = gv;
}

// ---------------------------------------------------------------------------
// Final: out[t] += routed[2t] + routed[2t+1]  (fixed order -> deterministic)
// ---------------------------------------------------------------------------
__global__ void final_add_kernel(float* __restrict__ out) {
    int i = blockIdx.x * blockDim.x + threadIdx.x;  // float4 index over T*HID/4
    if (i >= T_TOK * HID / 4) return;
    const int t  = i >> 8;          // HID/4 == 256 float4 per token
    const int d4 = i & 255;
    float4 o = ((const float4*)out)[i];
    float4 a = ((const float4*)(g_routed + (size_t)(2 * t) * HID))[d4];
    float4 b = ((const float4*)(g_routed + (size_t)(2 * t + 1) * HID))[d4];
    o.x += a.x + b.x;
    o.y += a.y + b.y;
    o.z += a.z + b.z;
    o.w += a.w + b.w;
    ((float4*)out)[i] = o;
}

// ---------------------------------------------------------------------------
// Launch
// ---------------------------------------------------------------------------
extern "C" void kernel_launch(void* const* d_in, const int* in_sizes, int n_in,
                              void* d_out, int out_size) {
    const float* x  = (const float*)d_in[0];  // [1,4096,1024]
    const float* rw = (const float*)d_in[1];  // [1024,16]
    const float* eg = (const float*)d_in[2];  // [16,1024,512]
    const float* eu = (const float*)d_in[3];  // [16,1024,512]
    const float* ed = (const float*)d_in[4];  // [16,512,1024]
    const float* sg = (const float*)d_in[5];  // [1024,2048]
    const float* su = (const float*)d_in[6];  // [1024,2048]
    const float* sd = (const float*)d_in[7];  // [2048,1024]
    float* out = (float*)d_out;               // [1,4096,1024]

    void *p_gate_s, *p_up_s, *p_gate_r, *p_up_r, *p_routed;
    cudaGetSymbolAddress(&p_gate_s, g_gate_s);
    cudaGetSymbolAddress(&p_up_s,   g_up_s);
    cudaGetSymbolAddress(&p_gate_r, g_gate_r);
    cudaGetSymbolAddress(&p_up_r,   g_up_r);
    cudaGetSymbolAddress(&p_routed, g_routed);

    // Routing
    zero_counts_kernel<<<1, 32>>>();
    router_kernel<<<T_TOK / 4, 128>>>(x, rw);

    // Shared expert: gate, up -> silu*mul -> down (writes base of d_out)
    sgemm128_kernel<0><<<dim3(FS / 128, T_TOK / 128, 1), 256>>>(
        x, sg, (float*)p_gate_s, T_TOK, FS, HID);
    sgemm128_kernel<0><<<dim3(FS / 128, T_TOK / 128, 1), 256>>>(
        x, su, (float*)p_up_s, T_TOK, FS, HID);
    silu_mul_kernel<<<(T_TOK * FS / 4) / 256, 256>>>(
        (float*)p_gate_s, (const float*)p_up_s, T_TOK * FS / 4);
    sgemm128_kernel<0><<<dim3(HID / 128, T_TOK / 128, 1), 256>>>(
        (const float*)p_gate_s, sd, out, T_TOK, HID, FS);

    // Routed experts: gather per expert, gate/up -> silu*mul -> down (scaled,
    // scattered per pair)
    sgemm128_kernel<1><<<dim3(FE / 128, T_TOK / 128, NE), 256>>>(
        x, eg, (float*)p_gate_r, 0, FE, HID);
    sgemm128_kernel<1><<<dim3(FE / 128, T_TOK / 128, NE), 256>>>(
        x, eu, (float*)p_up_r, 0, FE, HID);
    silu_mul_kernel<<<(NPAIR * FE / 4) / 256, 256>>>(
        (float*)p_gate_r, (const float*)p_up_r, NPAIR * FE / 4);
    sgemm128_kernel<2><<<dim3(HID / 128, T_TOK / 128, NE), 256>>>(
        (const float*)p_gate_r, ed, (float*)p_routed, 0, HID, FE);

    // out = shared_out + routed(pair0) + routed(pair1)
    final_add_kernel<<<(T_TOK * HID / 4) / 256, 256>>>(out);
}

// round 2
// speedup vs baseline: 1.1678x; 1.1678x over previous
#include <cuda_runtime.h>
#include <math.h>
#include <stdint.h>

// Problem constants (fixed by the dataset)
#define T_TOK 4096
#define HID   1024
#define NE    16
#define FE    512
#define FS    2048
#define NPAIR (T_TOK * 2)

// ---------------------------------------------------------------------------
// Scratch: __device__ globals (allocation-free per harness rules)
// ---------------------------------------------------------------------------
__device__ float g_gate_s[(size_t)T_TOK * FS];
__device__ float g_up_s[(size_t)T_TOK * FS];
__device__ float g_gate_r[(size_t)NPAIR * FE];
__device__ float g_up_r[(size_t)NPAIR * FE];
__device__ float g_routed[(size_t)NPAIR * HID];
__device__ int   g_cnt[NE];
__device__ int   g_bucket[NE * T_TOK];
__device__ float g_pw[NPAIR];

// ---------------------------------------------------------------------------
// Router (unchanged from round 1 — correct & cheap)
// ---------------------------------------------------------------------------
__global__ void zero_counts_kernel() {
    if (threadIdx.x < NE) g_cnt[threadIdx.x] = 0;
}

__global__ void router_kernel(const float* __restrict__ x,
                              const float* __restrict__ rw) {
    int warp = threadIdx.x >> 5;
    int lane = threadIdx.x & 31;
    int t = blockIdx.x * (blockDim.x >> 5) + warp;
    if (t >= T_TOK) return;

    float acc[NE];
#pragma unroll
    for (int e = 0; e < NE; e++) acc[e] = 0.0f;

    const float* xr = x + (size_t)t * HID;
    for (int d = lane; d < HID; d += 32) {
        float xv = xr[d];
        const float* r = rw + (size_t)d * NE;
#pragma unroll
        for (int e = 0; e < NE; e++) acc[e] = fmaf(xv, r[e], acc[e]);
    }
#pragma unroll
    for (int e = 0; e < NE; e++) {
#pragma unroll
        for (int off = 16; off; off >>= 1)
            acc[e] += __shfl_xor_sync(0xffffffffu, acc[e], off);
    }

    if (lane == 0) {
        float mx = acc[0];
#pragma unroll
        for (int e = 1; e < NE; e++) mx = fmaxf(mx, acc[e]);
        float p[NE];
        float s = 0.0f;
#pragma unroll
        for (int e = 0; e < NE; e++) { p[e] = expf(acc[e] - mx); s += p[e]; }
        float inv = 1.0f / s;
#pragma unroll
        for (int e = 0; e < NE; e++) p[e] *= inv;

        int   i0 = 0; float w0 = p[0];
#pragma unroll
        for (int e = 1; e < NE; e++) if (p[e] > w0) { w0 = p[e]; i0 = e; }
        int   i1 = -1; float w1 = -1.0f;
#pragma unroll
        for (int e = 0; e < NE; e++)
            if (e != i0 && p[e] > w1) { w1 = p[e]; i1 = e; }

        int pos0 = atomicAdd(&g_cnt[i0], 1);
        g_bucket[i0 * T_TOK + pos0] = 2 * t;
        int pos1 = atomicAdd(&g_cnt[i1], 1);
        g_bucket[i1 * T_TOK + pos1] = 2 * t + 1;
        g_pw[2 * t]     = w0;
        g_pw[2 * t + 1] = w1;
    }
}

// ---------------------------------------------------------------------------
// 3xTF32 split helpers + mma.sync wrapper
// ---------------------------------------------------------------------------
__device__ __forceinline__ void split_tf32(float v, uint32_t& hi, uint32_t& lo) {
    uint32_t h;
    asm("cvt.rna.tf32.f32 %0, %1;" : "=r"(h) : "f"(v));
    float r = v - __uint_as_float(h);
    uint32_t l;
    asm("cvt.rna.tf32.f32 %0, %1;" : "=r"(l) : "f"(r));
    hi = h; lo = l;
}

__device__ __forceinline__ void mma_tf32(float* d,
                                         const uint32_t* a,
                                         const uint32_t* b) {
    asm volatile(
        "mma.sync.aligned.m16n8k8.row.col.f32.tf32.tf32.f32 "
        "{%0,%1,%2,%3}, {%4,%5,%6,%7}, {%8,%9}, {%0,%1,%2,%3};\n"
        : "+f"(d[0]), "+f"(d[1]), "+f"(d[2]), "+f"(d[3])
        : "r"(a[0]), "r"(a[1]), "r"(a[2]), "r"(a[3]),
          "r"(b[0]), "r"(b[1]));
}

// ---------------------------------------------------------------------------
// Tensor-core GEMM 128x128x16, 256 threads (8 warps, each 64x32), 3xTF32.
// C[M,N] = A[M,K] @ B[K,N], row-major, fp32 in/out, ~fp32 accuracy.
// MODE 0: plain.  MODE 1: gather x rows by pair>>1, scatter by pair.
// MODE 2: gather inter rows by pair, scale by router weight, scatter by pair.
// ---------------------------------------------------------------------------
#define BM 128
#define BN 128
#define BK 16

template <int MODE>
__global__ __launch_bounds__(256)
void tgemm_kernel(const float* __restrict__ A,
                  const float* __restrict__ B,
                  float* __restrict__ C,
                  int M, int N, int K) {
    int e = blockIdx.z;
    int m_rows = M;
    const int* rowlist = nullptr;
    if (MODE != 0) {
        m_rows  = g_cnt[e];
        rowlist = g_bucket + e * T_TOK;
        B += (size_t)e * K * N;
    }
    const int m0 = blockIdx.y * BM;
    const int n0 = blockIdx.x * BN;
    if (m0 >= m_rows) return;

    __shared__ float As[2][BK][BM + 4];  // [k][m], padded
    __shared__ float Bs[2][BK][BN + 4];  // [k][n], padded

    const int tid  = threadIdx.x;
    const int lane = tid & 31;
    const int wid  = tid >> 5;
    const int warp_m = wid >> 2;          // 0..1
    const int warp_n = wid & 3;           // 0..3
    const int g  = lane >> 2;             // 0..7
    const int t4 = lane & 3;              // 0..3
    const int mb = warp_m * 64;           // warp m offset in tile
    const int nb = warp_n * 32;           // warp n offset in tile

    // --- loader mappings ---
    // A: thread -> (m = tid&127, kq = (tid>>7)*8), loads 8 consecutive k
    const int am = tid & 127;
    const int akq = (tid >> 7) * 8;
    // B: thread -> (kr = tid>>5 and kr+8, n4 = (tid&31)*4), float4 along n
    const int bkr = tid >> 5;             // 0..7
    const int bn4 = (tid & 31) * 4;

    const int  arow_g = m0 + am;
    const bool avalid = arow_g < m_rows;
    const int  aidx   = avalid ? arow_g : (m_rows - 1);
    const float* Arow;
    if (MODE == 0)      Arow = A + (size_t)aidx * K;
    else if (MODE == 1) Arow = A + (size_t)(rowlist[aidx] >> 1) * K;
    else                Arow = A + (size_t)rowlist[aidx] * K;

    // Prefetch stage 0
    {
        float4 a0v = make_float4(0, 0, 0, 0), a1v = make_float4(0, 0, 0, 0);
        if (avalid) {
            a0v = *(const float4*)(Arow + akq);
            a1v = *(const float4*)(Arow + akq + 4);
        }
        As[0][akq + 0][am] = a0v.x; As[0][akq + 1][am] = a0v.y;
        As[0][akq + 2][am] = a0v.z; As[0][akq + 3][am] = a0v.w;
        As[0][akq + 4][am] = a1v.x; As[0][akq + 5][am] = a1v.y;
        As[0][akq + 6][am] = a1v.z; As[0][akq + 7][am] = a1v.w;
        float4 b0v = *(const float4*)(B + (size_t)bkr * N + n0 + bn4);
        float4 b1v = *(const float4*)(B + (size_t)(bkr + 8) * N + n0 + bn4);
        *(float4*)&Bs[0][bkr][bn4]     = b0v;
        *(float4*)&Bs[0][bkr + 8][bn4] = b1v;
    }
    __syncthreads();

    float acc[4][4][4];
#pragma unroll
    for (int i = 0; i < 4; i++)
#pragma unroll
        for (int j = 0; j < 4; j++)
#pragma unroll
            for (int r = 0; r < 4; r++) acc[i][j][r] = 0.0f;

    const int KT = K / BK;
    float4 aP0, aP1, bP0, bP1;

    for (int kt = 0; kt < KT; kt++) {
        const int cur = kt & 1;
        if (kt + 1 < KT) {
            const int k0 = (kt + 1) * BK;
            aP0 = make_float4(0, 0, 0, 0); aP1 = make_float4(0, 0, 0, 0);
            if (avalid) {
                aP0 = *(const float4*)(Arow + k0 + akq);
                aP1 = *(const float4*)(Arow + k0 + akq + 4);
            }
            bP0 = *(const float4*)(B + (size_t)(k0 + bkr) * N + n0 + bn4);
            bP1 = *(const float4*)(B + (size_t)(k0 + bkr + 8) * N + n0 + bn4);
        }

#pragma unroll
        for (int kk0 = 0; kk0 < BK; kk0 += 8) {
            // B fragments (hi/lo) for all 4 n-tiles
            uint32_t bh[4][2], bl[4][2];
#pragma unroll
            for (int nt = 0; nt < 4; nt++) {
                float b0 = Bs[cur][kk0 + t4][nb + nt * 8 + g];
                float b1 = Bs[cur][kk0 + t4 + 4][nb + nt * 8 + g];
                split_tf32(b0, bh[nt][0], bl[nt][0]);
                split_tf32(b1, bh[nt][1], bl[nt][1]);
            }
            // A fragments per m-tile, 3 MMAs per (mt,nt)
#pragma unroll
            for (int mt = 0; mt < 4; mt++) {
                float a0 = As[cur][kk0 + t4][mb + mt * 16 + g];
                float a1 = As[cur][kk0 + t4][mb + mt * 16 + g + 8];
                float a2 = As[cur][kk0 + t4 + 4][mb + mt * 16 + g];
                float a3 = As[cur][kk0 + t4 + 4][mb + mt * 16 + g + 8];
                uint32_t ah[4], al[4];
                split_tf32(a0, ah[0], al[0]);
                split_tf32(a1, ah[1], al[1]);
                split_tf32(a2, ah[2], al[2]);
                split_tf32(a3, ah[3], al[3]);
#pragma unroll
                for (int nt = 0; nt < 4; nt++) {
                    mma_tf32(acc[mt][nt], ah, bh[nt]);
                    mma_tf32(acc[mt][nt], ah, bl[nt]);
                    mma_tf32(acc[mt][nt], al, bh[nt]);
                }
            }
        }

        if (kt + 1 < KT) {
            const int nxt = cur ^ 1;
            As[nxt][akq + 0][am] = aP0.x; As[nxt][akq + 1][am] = aP0.y;
            As[nxt][akq + 2][am] = aP0.z; As[nxt][akq + 3][am] = aP0.w;
            As[nxt][akq + 4][am] = aP1.x; As[nxt][akq + 5][am] = aP1.y;
            As[nxt][akq + 6][am] = aP1.z; As[nxt][akq + 7][am] = aP1.w;
            *(float4*)&Bs[nxt][bkr][bn4]     = bP0;
            *(float4*)&Bs[nxt][bkr + 8][bn4] = bP1;
        }
        __syncthreads();
    }

    // Epilogue: each thread owns rows (g, g+8) x cols (2*t4, 2*t4+1) per tile
#pragma unroll
    for (int mt = 0; mt < 4; mt++) {
        const int r0 = m0 + mb + mt * 16 + g;
        const int r1 = r0 + 8;
        float* Crow0 = nullptr; float* Crow1 = nullptr;
        float s0 = 1.0f, s1 = 1.0f;
        if (r0 < m_rows) {
            if (MODE == 0) Crow0 = C + (size_t)r0 * N;
            else {
                const int p = rowlist[r0];
                Crow0 = C + (size_t)p * N;
                if (MODE == 2) s0 = g_pw[p];
            }
        }
        if (r1 < m_rows) {
            if (MODE == 0) Crow1 = C + (size_t)r1 * N;
            else {
                const int p = rowlist[r1];
                Crow1 = C + (size_t)p * N;
                if (MODE == 2) s1 = g_pw[p];
            }
        }
#pragma unroll
        for (int nt = 0; nt < 4; nt++) {
            const int c = n0 + nb + nt * 8 + 2 * t4;
            if (Crow0) {
                float2 v = make_float2(acc[mt][nt][0] * s0, acc[mt][nt][1] * s0);
                *(float2*)(Crow0 + c) = v;
            }
            if (Crow1) {
                float2 v = make_float2(acc[mt][nt][2] * s1, acc[mt][nt][3] * s1);
                *(float2*)(Crow1 + c) = v;
            }
        }
    }
}

// ---------------------------------------------------------------------------
// Elementwise: g = silu(g) * u  (in-place into g)
// ---------------------------------------------------------------------------
__global__ void silu_mul_kernel(float* __restrict__ g,
                                const float* __restrict__ u, int n4) {
    int i = blockIdx.x * blockDim.x + threadIdx.x;
    if (i >= n4) return;
    float4 gv = ((const float4*)g)[i];
    float4 uv = ((const float4*)u)[i];
    gv.x = gv.x / (1.0f + expf(-gv.x)) * uv.x;
    gv.y = gv.y / (1.0f + expf(-gv.y)) * uv.y;
    gv.z = gv.z / (1.0f + expf(-gv.z)) * uv.z;
    gv.w = gv.w / (1.0f + expf(-gv.w)) * uv.w;
    ((float4*)g)[i] = gv;
}

// ---------------------------------------------------------------------------
// Final: out[t] += routed[2t] + routed[2t+1]
// ---------------------------------------------------------------------------
__global__ void final_add_kernel(float* __restrict__ out) {
    int i = blockIdx.x * blockDim.x + threadIdx.x;
    if (i >= T_TOK * HID / 4) return;
    const int t  = i >> 8;
    const int d4 = i & 255;
    float4 o = ((const float4*)out)[i];
    float4 a = ((const float4*)(g_routed + (size_t)(2 * t) * HID))[d4];
    float4 b = ((const float4*)(g_routed + (size_t)(2 * t + 1) * HID))[d4];
    o.x += a.x + b.x;
    o.y += a.y + b.y;
    o.z += a.z + b.z;
    o.w += a.w + b.w;
    ((float4*)out)[i] = o;
}

// ---------------------------------------------------------------------------
// Launch
// ---------------------------------------------------------------------------
extern "C" void kernel_launch(void* const* d_in, const int* in_sizes, int n_in,
                              void* d_out, int out_size) {
    const float* x  = (const float*)d_in[0];
    const float* rw = (const float*)d_in[1];
    const float* eg = (const float*)d_in[2];
    const float* eu = (const float*)d_in[3];
    const float* ed = (const float*)d_in[4];
    const float* sg = (const float*)d_in[5];
    const float* su = (const float*)d_in[6];
    const float* sd = (const float*)d_in[7];
    float* out = (float*)d_out;

    void *p_gate_s, *p_up_s, *p_gate_r, *p_up_r, *p_routed;
    cudaGetSymbolAddress(&p_gate_s, g_gate_s);
    cudaGetSymbolAddress(&p_up_s,   g_up_s);
    cudaGetSymbolAddress(&p_gate_r, g_gate_r);
    cudaGetSymbolAddress(&p_up_r,   g_up_r);
    cudaGetSymbolAddress(&p_routed, g_routed);

    zero_counts_kernel<<<1, 32>>>();
    router_kernel<<<T_TOK / 4, 128>>>(x, rw);

    // Shared expert
    tgemm_kernel<0><<<dim3(FS / BN, T_TOK / BM, 1), 256>>>(
        x, sg, (float*)p_gate_s, T_TOK, FS, HID);
    tgemm_kernel<0><<<dim3(FS / BN, T_TOK / BM, 1), 256>>>(
        x, su, (float*)p_up_s, T_TOK, FS, HID);
    silu_mul_kernel<<<(T_TOK * FS / 4) / 256, 256>>>(
        (float*)p_gate_s, (const float*)p_up_s, T_TOK * FS / 4);
    tgemm_kernel<0><<<dim3(HID / BN, T_TOK / BM, 1), 256>>>(
        (const float*)p_gate_s, sd, out, T_TOK, HID, FS);

    // Routed experts
    tgemm_kernel<1><<<dim3(FE / BN, T_TOK / BM, NE), 256>>>(
        x, eg, (float*)p_gate_r, 0, FE, HID);
    tgemm_kernel<1><<<dim3(FE / BN, T_TOK / BM, NE), 256>>>(
        x, eu, (float*)p_up_r, 0, FE, HID);
    silu_mul_kernel<<<(NPAIR * FE / 4) / 256, 256>>>(
        (float*)p_gate_r, (const float*)p_up_r, NPAIR * FE / 4);
    tgemm_kernel<2><<<dim3(HID / BN, T_TOK / BM, NE), 256>>>(
        (const float*)p_gate_r, ed, (float*)p_routed, 0, HID, FE);

    final_add_kernel<<<(T_TOK * HID / 4) / 256, 256>>>(out);
}

// round 4
// speedup vs baseline: 1.3805x; 1.1822x over previous
#include <cuda_runtime.h>
#include <math.h>
#include <stdint.h>

// Problem constants (fixed by the dataset)
#define T_TOK 4096
#define HID   1024
#define NE    16
#define FE    512
#define FS    2048
#define NPAIR (T_TOK * 2)

// ---------------------------------------------------------------------------
// Scratch: __device__ globals (allocation-free per harness rules)
// ---------------------------------------------------------------------------
__device__ float g_gate_s[(size_t)T_TOK * FS];
__device__ float g_up_s[(size_t)T_TOK * FS];
__device__ float g_gate_r[(size_t)NPAIR * FE];
__device__ float g_up_r[(size_t)NPAIR * FE];
__device__ float g_routed[(size_t)NPAIR * HID];
__device__ int   g_cnt[NE];
__device__ int   g_bucket[NE * T_TOK];
__device__ float g_pw[NPAIR];

// ---------------------------------------------------------------------------
// Router (validated rounds 1-2)
// ---------------------------------------------------------------------------
__global__ void zero_counts_kernel() {
    if (threadIdx.x < NE) g_cnt[threadIdx.x] = 0;
}

__global__ void router_kernel(const float* __restrict__ x,
                              const float* __restrict__ rw) {
    int warp = threadIdx.x >> 5;
    int lane = threadIdx.x & 31;
    int t = blockIdx.x * (blockDim.x >> 5) + warp;
    if (t >= T_TOK) return;

    float acc[NE];
#pragma unroll
    for (int e = 0; e < NE; e++) acc[e] = 0.0f;

    const float* xr = x + (size_t)t * HID;
    for (int d = lane; d < HID; d += 32) {
        float xv = xr[d];
        const float* r = rw + (size_t)d * NE;
#pragma unroll
        for (int e = 0; e < NE; e++) acc[e] = fmaf(xv, r[e], acc[e]);
    }
#pragma unroll
    for (int e = 0; e < NE; e++) {
#pragma unroll
        for (int off = 16; off; off >>= 1)
            acc[e] += __shfl_xor_sync(0xffffffffu, acc[e], off);
    }

    if (lane == 0) {
        float mx = acc[0];
#pragma unroll
        for (int e = 1; e < NE; e++) mx = fmaxf(mx, acc[e]);
        float p[NE];
        float s = 0.0f;
#pragma unroll
        for (int e = 0; e < NE; e++) { p[e] = expf(acc[e] - mx); s += p[e]; }
        float inv = 1.0f / s;
#pragma unroll
        for (int e = 0; e < NE; e++) p[e] *= inv;

        int   i0 = 0; float w0 = p[0];
#pragma unroll
        for (int e = 1; e < NE; e++) if (p[e] > w0) { w0 = p[e]; i0 = e; }
        int   i1 = -1; float w1 = -1.0f;
#pragma unroll
        for (int e = 0; e < NE; e++)
            if (e != i0 && p[e] > w1) { w1 = p[e]; i1 = e; }

        int pos0 = atomicAdd(&g_cnt[i0], 1);
        g_bucket[i0 * T_TOK + pos0] = 2 * t;
        int pos1 = atomicAdd(&g_cnt[i1], 1);
        g_bucket[i1 * T_TOK + pos1] = 2 * t + 1;
        g_pw[2 * t]     = w0;
        g_pw[2 * t + 1] = w1;
    }
}

// ---------------------------------------------------------------------------
// 3xTF32 split + mma.sync wrapper (layouts validated round 2)
// ---------------------------------------------------------------------------
__device__ __forceinline__ void split_tf32(float v, uint32_t& hi, uint32_t& lo) {
    uint32_t h;
    asm("cvt.rna.tf32.f32 %0, %1;" : "=r"(h) : "f"(v));
    float r = v - __uint_as_float(h);
    uint32_t l;
    asm("cvt.rna.tf32.f32 %0, %1;" : "=r"(l) : "f"(r));
    hi = h; lo = l;
}

__device__ __forceinline__ void mma_tf32(float* d,
                                         const uint32_t* a,
                                         const uint32_t* b) {
    asm volatile(
        "mma.sync.aligned.m16n8k8.row.col.f32.tf32.tf32.f32 "
        "{%0,%1,%2,%3}, {%4,%5,%6,%7}, {%8,%9}, {%0,%1,%2,%3};\n"
        : "+f"(d[0]), "+f"(d[1]), "+f"(d[2]), "+f"(d[3])
        : "r"(a[0]), "r"(a[1]), "r"(a[2]), "r"(a[3]),
          "r"(b[0]), "r"(b[1]));
}

// ---------------------------------------------------------------------------
// Tensor GEMM 128x128x16, 256 threads, producer-side hi/lo split.
// Smem (dynamic, per stage, in uint32):
//   Ah: [128][20]  (A hi, row-major, pad 4)   offset 0
//   Al: [128][20]                              offset 2560
//   Bh: [16][136]  (B hi, k-major, pad 8)      offset 5120
//   Bl: [16][136]                              offset 7296
//   stage stride 9472 (x2 stages = 75776 B)
// MODE 0: plain. MODE 1: gather x rows by pair>>1, scatter C by pair.
// MODE 2: gather rows by pair, scale C by router weight, scatter by pair.
// ---------------------------------------------------------------------------
#define BM 128
#define BN 128
#define BK 16
#define A_PAD 20
#define B_PAD 136
#define OFF_AL 2560
#define OFF_BH 5120
#define OFF_BL 7296
#define STAGEF 9472
#define SMEM_DYN (2 * STAGEF * 4)

template <int MODE>
__global__ __launch_bounds__(256, 2)
void tgemm_kernel(const float* __restrict__ A,
                  const float* __restrict__ B,
                  float* __restrict__ C,
                  int M, int N, int K) {
    int e = blockIdx.z;
    int m_rows = M;
    const int* rowlist = nullptr;
    if (MODE != 0) {
        m_rows  = g_cnt[e];
        rowlist = g_bucket + e * T_TOK;
        B += (size_t)e * K * N;
    }
    const int m0 = blockIdx.y * BM;
    const int n0 = blockIdx.x * BN;
    if (m0 >= m_rows) return;

    extern __shared__ uint32_t sm[];

    const int tid  = threadIdx.x;
    const int lane = tid & 31;
    const int wid  = tid >> 5;
    const int warp_m = wid >> 2;          // 0..1
    const int warp_n = wid & 3;           // 0..3
    const int g  = lane >> 2;             // 0..7
    const int t4 = lane & 3;              // 0..3
    const int mb = warp_m * 64;
    const int nb = warp_n * 32;

    // --- loader mappings ---
    // A: m = tid>>1 (0..127), k-octet = (tid&1)*8
    const int am  = tid >> 1;
    const int akq = (tid & 1) * 8;
    // B: k rows tid>>5 and (tid>>5)+8; n quad = (tid&31)*4
    const int bkr = tid >> 5;
    const int bn4 = (tid & 31) * 4;

    const int  ar_g = m0 + am;
    const bool av   = ar_g < m_rows;
    const int  aidx = av ? ar_g : 0;
    const float* Arow;
    if (MODE == 0)      Arow = A + (size_t)aidx * K;
    else if (MODE == 1) Arow = A + (size_t)(rowlist[aidx] >> 1) * K;
    else                Arow = A + (size_t)rowlist[aidx] * K;

    const float* Bp0 = B + (size_t)bkr * N + n0 + bn4;        // row bkr
    const float* Bp1 = B + (size_t)(bkr + 8) * N + n0 + bn4;  // row bkr+8

    // STS helper for one stage
    auto stage_store = [&](int s, float4 va0, float4 va1, float4 vb0, float4 vb1) {
        uint32_t* st = sm + s * STAGEF;
        uint32_t h0, l0, h1, l1, h2, l2, h3, l3;
        // A octet -> Ah/Al [am][akq..akq+7]
        split_tf32(va0.x, h0, l0); split_tf32(va0.y, h1, l1);
        split_tf32(va0.z, h2, l2); split_tf32(va0.w, h3, l3);
        *(uint4*)(st + am * A_PAD + akq)          = make_uint4(h0, h1, h2, h3);
        *(uint4*)(st + OFF_AL + am * A_PAD + akq) = make_uint4(l0, l1, l2, l3);
        split_tf32(va1.x, h0, l0); split_tf32(va1.y, h1, l1);
        split_tf32(va1.z, h2, l2); split_tf32(va1.w, h3, l3);
        *(uint4*)(st + am * A_PAD + akq + 4)          = make_uint4(h0, h1, h2, h3);
        *(uint4*)(st + OFF_AL + am * A_PAD + akq + 4) = make_uint4(l0, l1, l2, l3);
        // B rows -> Bh/Bl [bkr][bn4], [bkr+8][bn4]
        split_tf32(vb0.x, h0, l0); split_tf32(vb0.y, h1, l1);
        split_tf32(vb0.z, h2, l2); split_tf32(vb0.w, h3, l3);
        *(uint4*)(st + OFF_BH + bkr * B_PAD + bn4) = make_uint4(h0, h1, h2, h3);
        *(uint4*)(st + OFF_BL + bkr * B_PAD + bn4) = make_uint4(l0, l1, l2, l3);
        split_tf32(vb1.x, h0, l0); split_tf32(vb1.y, h1, l1);
        split_tf32(vb1.z, h2, l2); split_tf32(vb1.w, h3, l3);
        *(uint4*)(st + OFF_BH + (bkr + 8) * B_PAD + bn4) = make_uint4(h0, h1, h2, h3);
        *(uint4*)(st + OFF_BL + (bkr + 8) * B_PAD + bn4) = make_uint4(l0, l1, l2, l3);
    };

    // Prefetch stage 0
    {
        float4 va0 = make_float4(0, 0, 0, 0), va1 = va0;
        if (av) {
            va0 = *(const float4*)(Arow + akq);
            va1 = *(const float4*)(Arow + akq + 4);
        }
        float4 vb0 = *(const float4*)Bp0;
        float4 vb1 = *(const float4*)Bp1;
        stage_store(0, va0, va1, vb0, vb1);
    }
    __syncthreads();

    float acc[4][4][4];
#pragma unroll
    for (int i = 0; i < 4; i++)
#pragma unroll
        for (int j = 0; j < 4; j++)
#pragma unroll
            for (int r = 0; r < 4; r++) acc[i][j][r] = 0.0f;

    const int KT = K / BK;
    float4 va0, va1, vb0, vb1;

    for (int kt = 0; kt < KT; kt++) {
        const int cur = kt & 1;
        if (kt + 1 < KT) {
            const int k0 = (kt + 1) * BK;
            va0 = make_float4(0, 0, 0, 0); va1 = va0;
            if (av) {
                va0 = *(const float4*)(Arow + k0 + akq);
                va1 = *(const float4*)(Arow + k0 + akq + 4);
            }
            vb0 = *(const float4*)(Bp0 + (size_t)k0 * N);
            vb1 = *(const float4*)(Bp1 + (size_t)k0 * N);
        }

        const uint32_t* Ah = sm + cur * STAGEF;
        const uint32_t* Al = Ah + OFF_AL;
        const uint32_t* Bh = sm + cur * STAGEF + OFF_BH;
        const uint32_t* Bl = Bh + (OFF_BL - OFF_BH);

#pragma unroll
        for (int kk = 0; kk < BK; kk += 8) {
            uint32_t bh[4][2], bl[4][2];
#pragma unroll
            for (int nt = 0; nt < 4; nt++) {
                const int col = nb + nt * 8 + g;
                bh[nt][0] = Bh[(kk + t4) * B_PAD + col];
                bh[nt][1] = Bh[(kk + t4 + 4) * B_PAD + col];
                bl[nt][0] = Bl[(kk + t4) * B_PAD + col];
                bl[nt][1] = Bl[(kk + t4 + 4) * B_PAD + col];
            }
#pragma unroll
            for (int mt = 0; mt < 4; mt++) {
                const int r0 = (mb + mt * 16 + g) * A_PAD;
                const int r1 = r0 + 8 * A_PAD;
                uint32_t ah[4], al[4];
                ah[0] = Ah[r0 + kk + t4];
                ah[1] = Ah[r1 + kk + t4];
                ah[2] = Ah[r0 + kk + t4 + 4];
                ah[3] = Ah[r1 + kk + t4 + 4];
                al[0] = Al[r0 + kk + t4];
                al[1] = Al[r1 + kk + t4];
                al[2] = Al[r0 + kk + t4 + 4];
                al[3] = Al[r1 + kk + t4 + 4];
#pragma unroll
                for (int nt = 0; nt < 4; nt++) {
                    mma_tf32(acc[mt][nt], ah, bh[nt]);
                    mma_tf32(acc[mt][nt], ah, bl[nt]);
                    mma_tf32(acc[mt][nt], al, bh[nt]);
                }
            }
        }

        if (kt + 1 < KT) stage_store(cur ^ 1, va0, va1, vb0, vb1);
        __syncthreads();
    }

    // Epilogue (validated round 2)
#pragma unroll
    for (int mt = 0; mt < 4; mt++) {
        const int r0 = m0 + mb + mt * 16 + g;
        const int r1 = r0 + 8;
        float* Crow0 = nullptr; float* Crow1 = nullptr;
        float s0 = 1.0f, s1 = 1.0f;
        if (r0 < m_rows) {
            if (MODE == 0) Crow0 = C + (size_t)r0 * N;
            else {
                const int p = rowlist[r0];
                Crow0 = C + (size_t)p * N;
                if (MODE == 2) s0 = g_pw[p];
            }
        }
        if (r1 < m_rows) {
            if (MODE == 0) Crow1 = C + (size_t)r1 * N;
            else {
                const int p = rowlist[r1];
                Crow1 = C + (size_t)p * N;
                if (MODE == 2) s1 = g_pw[p];
            }
        }
#pragma unroll
        for (int nt = 0; nt < 4; nt++) {
            const int c = n0 + nb + nt * 8 + 2 * t4;
            if (Crow0) {
                float2 v = make_float2(acc[mt][nt][0] * s0, acc[mt][nt][1] * s0);
                *(float2*)(Crow0 + c) = v;
            }
            if (Crow1) {
                float2 v = make_float2(acc[mt][nt][2] * s1, acc[mt][nt][3] * s1);
                *(float2*)(Crow1 + c) = v;
            }
        }
    }
}

// ---------------------------------------------------------------------------
// Elementwise: g = silu(g) * u  (in-place into g)
// ---------------------------------------------------------------------------
__global__ void silu_mul_kernel(float* __restrict__ g,
                                const float* __restrict__ u, int n4) {
    int i = blockIdx.x * blockDim.x + threadIdx.x;
    if (i >= n4) return;
    float4 gv = ((const float4*)g)[i];
    float4 uv = ((const float4*)u)[i];
    gv.x = gv.x / (1.0f + expf(-gv.x)) * uv.x;
    gv.y = gv.y / (1.0f + expf(-gv.y)) * uv.y;
    gv.z = gv.z / (1.0f + expf(-gv.z)) * uv.z;
    gv.w = gv.w / (1.0f + expf(-gv.w)) * uv.w;
    ((float4*)g)[i] = gv;
}

// ---------------------------------------------------------------------------
// Final: out[t] += routed[2t] + routed[2t+1]
// ---------------------------------------------------------------------------
__global__ void final_add_kernel(float* __restrict__ out) {
    int i = blockIdx.x * blockDim.x + threadIdx.x;
    if (i >= T_TOK * HID / 4) return;
    const int t  = i >> 8;
    const int d4 = i & 255;
    float4 o = ((const float4*)out)[i];
    float4 a = ((const float4*)(g_routed + (size_t)(2 * t) * HID))[d4];
    float4 b = ((const float4*)(g_routed + (size_t)(2 * t + 1) * HID))[d4];
    o.x += a.x + b.x;
    o.y += a.y + b.y;
    o.z += a.z + b.z;
    o.w += a.w + b.w;
    ((float4*)out)[i] = o;
}

// ---------------------------------------------------------------------------
// Launch
// ---------------------------------------------------------------------------
extern "C" void kernel_launch(void* const* d_in, const int* in_sizes, int n_in,
                              void* d_out, int out_size) {
    const float* x  = (const float*)d_in[0];
    const float* rw = (const float*)d_in[1];
    const float* eg = (const float*)d_in[2];
    const float* eu = (const float*)d_in[3];
    const float* ed = (const float*)d_in[4];
    const float* sg = (const float*)d_in[5];
    const float* su = (const float*)d_in[6];
    const float* sd = (const float*)d_in[7];
    float* out = (float*)d_out;

    void *p_gate_s, *p_up_s, *p_gate_r, *p_up_r, *p_routed;
    cudaGetSymbolAddress(&p_gate_s, g_gate_s);
    cudaGetSymbolAddress(&p_up_s,   g_up_s);
    cudaGetSymbolAddress(&p_gate_r, g_gate_r);
    cudaGetSymbolAddress(&p_up_r,   g_up_r);
    cudaGetSymbolAddress(&p_routed, g_routed);

    cudaFuncSetAttribute(tgemm_kernel<0>,
                         cudaFuncAttributeMaxDynamicSharedMemorySize, SMEM_DYN);
    cudaFuncSetAttribute(tgemm_kernel<1>,
                         cudaFuncAttributeMaxDynamicSharedMemorySize, SMEM_DYN);
    cudaFuncSetAttribute(tgemm_kernel<2>,
                         cudaFuncAttributeMaxDynamicSharedMemorySize, SMEM_DYN);

    zero_counts_kernel<<<1, 32>>>();
    router_kernel<<<T_TOK / 4, 128>>>(x, rw);

    // Shared expert
    tgemm_kernel<0><<<dim3(FS / BN, T_TOK / BM, 1), 256, SMEM_DYN>>>(
        x, sg, (float*)p_gate_s, T_TOK, FS, HID);
    tgemm_kernel<0><<<dim3(FS / BN, T_TOK / BM, 1), 256, SMEM_DYN>>>(
        x, su, (float*)p_up_s, T_TOK, FS, HID);
    silu_mul_kernel<<<(T_TOK * FS / 4) / 256, 256>>>(
        (float*)p_gate_s, (const float*)p_up_s, T_TOK * FS / 4);
    tgemm_kernel<0><<<dim3(HID / BN, T_TOK / BM, 1), 256, SMEM_DYN>>>(
        (const float*)p_gate_s, sd, out, T_TOK, HID, FS);

    // Routed experts
    tgemm_kernel<1><<<dim3(FE / BN, T_TOK / BM, NE), 256, SMEM_DYN>>>(
        x, eg, (float*)p_gate_r, 0, FE, HID);
    tgemm_kernel<1><<<dim3(FE / BN, T_TOK / BM, NE), 256, SMEM_DYN>>>(
        x, eu, (float*)p_up_r, 0, FE, HID);
    silu_mul_kernel<<<(NPAIR * FE / 4) / 256, 256>>>(
        (float*)p_gate_r, (const float*)p_up_r, NPAIR * FE / 4);
    tgemm_kernel<2><<<dim3(HID / BN, T_TOK / BM, NE), 256, SMEM_DYN>>>(
        (const float*)p_gate_r, ed, (float*)p_routed, 0, HID, FE);

    final_add_kernel<<<(T_TOK * HID / 4) / 256, 256>>>(out);
}